// round 3
// baseline (speedup 1.0000x reference)
#include <cuda_runtime.h>
#include <cuda_bf16.h>

// TransferMatrixMethod: B=256, L=64 (62 interior), W=512.
// Layer matrices [[a, ib],[ic, d]] (real a,b,c,d) closed under multiplication:
// track real A,B,C,D with M=[[A,iB],[iC,D]], plus Dt=-D so all updates share
// one form:  X' = cp*X + m*Y  with m in {ns, msr}:
//   A' = cp*A + ns*B
//   B' = cp*B + msr*A        (msr = -sin/(n+1e-8))
//   C' = cp*C + ns*Dt        (Dt = -D:  C' = cp*C - ns*D)
//   Dt'= cp*Dt + msr*C       (=> D' = cp*D + sr*C)
//
// f32x2 lanes = TWO ADJACENT WAVELENGTHS per thread (no lane duplication).
//
// Epilogue: E=(A+1e-9)+i*B*nsub, H=D*nsub+i*C,
//   r=(nin*E-H)/(nin*E+H), R=|num|^2/|den|^2 -> one division per point.

#define NLAYERS 62
#define LTOT    64
#define WDIM    512
#define TPB     64

typedef unsigned long long u64;

__device__ __forceinline__ u64 pack2(float lo, float hi) {
    u64 r;
    asm("mov.b64 %0, {%1, %2};" : "=l"(r) : "f"(lo), "f"(hi));
    return r;
}
__device__ __forceinline__ void unpack2(float& lo, float& hi, u64 v) {
    asm("mov.b64 {%0, %1}, %2;" : "=f"(lo), "=f"(hi) : "l"(v));
}
__device__ __forceinline__ u64 mul2(u64 a, u64 b) {
    u64 r;
    asm("mul.rn.f32x2 %0, %1, %2;" : "=l"(r) : "l"(a), "l"(b));
    return r;
}
__device__ __forceinline__ u64 fma2(u64 a, u64 b, u64 c) {
    u64 r;
    asm("fma.rn.f32x2 %0, %1, %2, %3;" : "=l"(r) : "l"(a), "l"(b), "l"(c));
    return r;
}

__global__ __launch_bounds__(TPB)
void tmm_kernel(const float* __restrict__ n_layers,
                const float* __restrict__ d_layers,
                const float* __restrict__ wavelengths,
                float* __restrict__ out)
{
    const int b  = blockIdx.x >> 2;             // 0..255
    const int q  = blockIdx.x & 3;              // quarter of wavelength axis
    const int t  = threadIdx.x;                 // 0..63
    const int w0 = (q * TPB + t) * 2;           // even wavelength index

    __shared__ u64 s_nd2[NLAYERS];   // {n*d, n*d}
    __shared__ u64 s_n2[NLAYERS];    // {n, n}
    __shared__ u64 s_mr2[NLAYERS];   // {-1/(n+eps), -1/(n+eps)}
    __shared__ float s_nin, s_nsub;

    const float* nrow = n_layers + b * LTOT;
    const float* drow = d_layers + b * LTOT;

    if (t < NLAYERS) {
        float nv = nrow[t + 1];
        float dv = drow[t + 1];
        float nd = nv * dv;
        s_nd2[t] = pack2(nd, nd);
        s_n2[t]  = pack2(nv, nv);
        float mr = -1.0f / (nv + 1e-8f);
        s_mr2[t] = pack2(mr, mr);
    }
    if (t == NLAYERS)     s_nin  = nrow[0];
    if (t == NLAYERS + 1) s_nsub = nrow[LTOT - 1];
    __syncthreads();

    const float TWO_PI = 6.28318530717958647692f;
    const float2 lam = *reinterpret_cast<const float2*>(wavelengths + w0);
    const u64 k02 = pack2(TWO_PI / lam.x, TWO_PI / lam.y);

    u64 A  = pack2(1.0f, 1.0f);
    u64 Bv = pack2(0.0f, 0.0f);
    u64 C  = pack2(0.0f, 0.0f);
    u64 Dt = pack2(-1.0f, -1.0f);   // -D

    #pragma unroll
    for (int l = 0; l < NLAYERS; ++l) {
        u64 phi2 = mul2(s_nd2[l], k02);   // |phi| <= ~12: within MUFU.SIN range
        float p0, p1;
        unpack2(p0, p1, phi2);
        float sp0, cp0, sp1, cp1;
        __sincosf(p0, &sp0, &cp0);
        __sincosf(p1, &sp1, &cp1);
        u64 sp2 = pack2(sp0, sp1);
        u64 cp2 = pack2(cp0, cp1);

        u64 ns2  = mul2(sp2, s_n2[l]);    // { n*sin }
        u64 msr2 = mul2(sp2, s_mr2[l]);   // { -sin/(n+eps) }

        u64 nA = fma2(ns2,  Bv, mul2(cp2, A));
        u64 nB = fma2(msr2, A,  mul2(cp2, Bv));
        u64 nC = fma2(ns2,  Dt, mul2(cp2, C));
        u64 nD = fma2(msr2, C,  mul2(cp2, Dt));
        A = nA; Bv = nB; C = nC; Dt = nD;
    }

    float A0, A1, B0, B1, C0, C1, Dt0, Dt1;
    unpack2(A0, A1, A);
    unpack2(B0, B1, Bv);
    unpack2(C0, C1, C);
    unpack2(Dt0, Dt1, Dt);

    const float nin  = s_nin;
    const float nsub = s_nsub;

    float R[2];
    #pragma unroll
    for (int i = 0; i < 2; ++i) {
        const float a = i ? A1 : A0;
        const float bb = i ? B1 : B0;
        const float c = i ? C1 : C0;
        const float d = -(i ? Dt1 : Dt0);

        const float Er = a + 1e-9f;
        const float Ei = bb * nsub;
        const float Hr = d * nsub;
        const float Hi = c;

        const float numr = fmaf(nin, Er, -Hr);
        const float numi = fmaf(nin, Ei, -Hi);
        const float denr = fmaf(nin, Er,  Hr);
        const float deni = fmaf(nin, Ei,  Hi);

        const float num2 = fmaf(numr, numr, numi * numi);
        const float den2 = fmaf(denr, denr, deni * deni);
        R[i] = num2 / den2;
    }

    *reinterpret_cast<float2*>(out + b * WDIM + w0) = make_float2(R[0], R[1]);
}

extern "C" void kernel_launch(void* const* d_in, const int* in_sizes, int n_in,
                              void* d_out, int out_size)
{
    const float* n_layers    = (const float*)d_in[0];  // (256, 64)
    const float* d_layers    = (const float*)d_in[1];  // (256, 64)
    const float* wavelengths = (const float*)d_in[2];  // (512,)
    float* out = (float*)d_out;                        // (256, 512)

    tmm_kernel<<<1024, TPB>>>(n_layers, d_layers, wavelengths, out);
}

// round 4
// speedup vs baseline: 1.0539x; 1.0539x over previous
#include <cuda_runtime.h>
#include <cuda_bf16.h>

// TransferMatrixMethod: B=256, L=64 (62 interior), W=512.
// Layer matrices [[a, ib],[ic, d]] (real a,b,c,d) are closed under
// multiplication. Track A,B,C,Dt(=-D), f32x2 lanes = 2 adjacent wavelengths.
// Per-layer update (m in {ns, msr}):  X' = cp*X + m*Y.
//
// PARALLEL SPLIT: M_total = (M1..M31) * (M32..M62). Lane lid<16 computes the
// first half, lane lid>=16 (same chain, xor 16) the second half; combine via
// shuffle:  [X*Y]: A = Ax*Ay - Bx*Cy,  B = Ax*By + Bx*Dy,
//            C = Cx*Ay + Dx*Cy,  D = Dx*Dy - Cx*By   (Dy=-Dty, Dx=-Dtx)
//
// Epilogue: E=(A+1e-9)+i*B*nsub, H=D*nsub+i*C,
//   r=(nin*E-H)/(nin*E+H), R=|num|^2/|den|^2 -> one division per point.

#define NLAYERS 62
#define HALF_L  31
#define LTOT    64
#define WDIM    512
#define TPB     128   // 4 warps; 64 chains/block; 128 wavelengths/block

typedef unsigned long long u64;

__device__ __forceinline__ u64 pack2(float lo, float hi) {
    u64 r;
    asm("mov.b64 %0, {%1, %2};" : "=l"(r) : "f"(lo), "f"(hi));
    return r;
}
__device__ __forceinline__ void unpack2(float& lo, float& hi, u64 v) {
    asm("mov.b64 {%0, %1}, %2;" : "=f"(lo), "=f"(hi) : "l"(v));
}
__device__ __forceinline__ u64 mul2(u64 a, u64 b) {
    u64 r;
    asm("mul.rn.f32x2 %0, %1, %2;" : "=l"(r) : "l"(a), "l"(b));
    return r;
}
__device__ __forceinline__ u64 fma2(u64 a, u64 b, u64 c) {
    u64 r;
    asm("fma.rn.f32x2 %0, %1, %2, %3;" : "=l"(r) : "l"(a), "l"(b), "l"(c));
    return r;
}
__device__ __forceinline__ u64 neg2(u64 a) {
    // negate both f32 lanes by XORing sign bits
    return a ^ 0x8000000080000000ULL;
}

__global__ __launch_bounds__(TPB)
void tmm_kernel(const float* __restrict__ n_layers,
                const float* __restrict__ d_layers,
                const float* __restrict__ wavelengths,
                float* __restrict__ out)
{
    const int b   = blockIdx.x >> 2;            // 0..255
    const int q   = blockIdx.x & 3;             // quarter of wavelength axis
    const int t   = threadIdx.x;                // 0..127
    const int lid = t & 31;
    const int wrp = t >> 5;                     // warp in block, 0..3
    const int half  = lid >> 4;                 // 0: layers 0..30, 1: 31..61
    const int chain = wrp * 16 + (lid & 15);    // 0..63 within block
    const int w0    = (q * 64 + chain) * 2;     // even wavelength index

    __shared__ u64 s_nd2[NLAYERS];   // {n*d, n*d}
    __shared__ u64 s_n2[NLAYERS];    // {n, n}
    __shared__ u64 s_mr2[NLAYERS];   // {-1/(n+eps), -1/(n+eps)}
    __shared__ float s_nin, s_nsub;

    const float* nrow = n_layers + b * LTOT;
    const float* drow = d_layers + b * LTOT;

    if (t < NLAYERS) {
        float nv = nrow[t + 1];
        float dv = drow[t + 1];
        float nd = nv * dv;
        s_nd2[t] = pack2(nd, nd);
        s_n2[t]  = pack2(nv, nv);
        float mr = -1.0f / (nv + 1e-8f);
        s_mr2[t] = pack2(mr, mr);
    }
    if (t == NLAYERS)     s_nin  = nrow[0];
    if (t == NLAYERS + 1) s_nsub = nrow[LTOT - 1];
    __syncthreads();

    const float TWO_PI = 6.28318530717958647692f;
    const float2 lam = *reinterpret_cast<const float2*>(wavelengths + w0);
    const u64 k02 = pack2(TWO_PI / lam.x, TWO_PI / lam.y);

    const int base = half * HALF_L;

    u64 A  = pack2(1.0f, 1.0f);
    u64 Bv = pack2(0.0f, 0.0f);
    u64 C  = pack2(0.0f, 0.0f);
    u64 Dt = pack2(-1.0f, -1.0f);   // -D

    #pragma unroll
    for (int l = 0; l < HALF_L; ++l) {
        u64 phi2 = mul2(s_nd2[base + l], k02);  // |phi| <= ~12: MUFU-safe
        float p0, p1;
        unpack2(p0, p1, phi2);
        float sp0, cp0, sp1, cp1;
        __sincosf(p0, &sp0, &cp0);
        __sincosf(p1, &sp1, &cp1);
        u64 sp2 = pack2(sp0, sp1);
        u64 cp2 = pack2(cp0, cp1);

        u64 ns2  = mul2(sp2, s_n2[base + l]);   // { n*sin }
        u64 msr2 = mul2(sp2, s_mr2[base + l]);  // { -sin/(n+eps) }

        u64 nA = fma2(ns2,  Bv, mul2(cp2, A));
        u64 nB = fma2(msr2, A,  mul2(cp2, Bv));
        u64 nC = fma2(ns2,  Dt, mul2(cp2, C));
        u64 nD = fma2(msr2, C,  mul2(cp2, Dt));
        A = nA; Bv = nB; C = nC; Dt = nD;
    }

    // exchange halves: lane i <-> lane i^16
    const unsigned FULL = 0xffffffffu;
    u64 Ay  = __shfl_xor_sync(FULL, A,  16);
    u64 By  = __shfl_xor_sync(FULL, Bv, 16);
    u64 Cy  = __shfl_xor_sync(FULL, C,  16);
    u64 Dty = __shfl_xor_sync(FULL, Dt, 16);

    if (half == 0) {
        // combine: M = X * Y   (X = own = layers 1..31, Y = partner)
        u64 Dy = neg2(Dty);
        u64 fA = fma2(neg2(Bv), Cy, mul2(A, Ay));       // Ax*Ay - Bx*Cy
        u64 fB = fma2(Bv, Dy,       mul2(A, By));       // Ax*By + Bx*Dy
        u64 fC = fma2(neg2(Dt), Cy, mul2(C, Ay));       // Cx*Ay + Dx*Cy (Dx=-Dtx)
        u64 fD = fma2(neg2(C),  By, mul2(neg2(Dt), Dy));// Dx*Dy - Cx*By

        float A0, A1, B0, B1, C0, C1, D0, D1;
        unpack2(A0, A1, fA);
        unpack2(B0, B1, fB);
        unpack2(C0, C1, fC);
        unpack2(D0, D1, fD);

        const float nin  = s_nin;
        const float nsub = s_nsub;

        float R[2];
        #pragma unroll
        for (int i = 0; i < 2; ++i) {
            const float a  = i ? A1 : A0;
            const float bb = i ? B1 : B0;
            const float c  = i ? C1 : C0;
            const float d  = i ? D1 : D0;

            const float Er = a + 1e-9f;
            const float Ei = bb * nsub;
            const float Hr = d * nsub;
            const float Hi = c;

            const float numr = fmaf(nin, Er, -Hr);
            const float numi = fmaf(nin, Ei, -Hi);
            const float denr = fmaf(nin, Er,  Hr);
            const float deni = fmaf(nin, Ei,  Hi);

            const float num2 = fmaf(numr, numr, numi * numi);
            const float den2 = fmaf(denr, denr, deni * deni);
            R[i] = num2 / den2;
        }

        *reinterpret_cast<float2*>(out + b * WDIM + w0) = make_float2(R[0], R[1]);
    }
}

extern "C" void kernel_launch(void* const* d_in, const int* in_sizes, int n_in,
                              void* d_out, int out_size)
{
    const float* n_layers    = (const float*)d_in[0];  // (256, 64)
    const float* d_layers    = (const float*)d_in[1];  // (256, 64)
    const float* wavelengths = (const float*)d_in[2];  // (512,)
    float* out = (float*)d_out;                        // (256, 512)

    tmm_kernel<<<1024, TPB>>>(n_layers, d_layers, wavelengths, out);
}